// round 7
// baseline (speedup 1.0000x reference)
#include <cuda_runtime.h>

#define B_ 2048
#define N_ 80
#define T_ 400
#define BN_ (B_ * N_)

// Full-range approximate fp32 division (div.full.f32) — the instruction XLA's
// GPU elemental emitter uses for fp32 divide (not IEEE div.rn).
__device__ __forceinline__ float div_full(float a, float b) {
    float r;
    asm("div.full.f32 %0, %1, %2;" : "=f"(r) : "f"(a), "f"(b));
    return r;
}

// LIF step matching the reference's fp32 op order (division via div.full).
#define STEP(vv, rff, iss, add, nn, tau, th, dr, rs, SP)                          \
    {                                                                              \
        float it_  = __fadd_rn(__fsub_rn(__fadd_rn(iss, dr), add),                 \
                               __fmul_rn(nn, 0.5f));                               \
        float act_ = (rff <= 0.0f) ? 1.0f : 0.0f;                                  \
        float dv_  = __fmul_rn(__fmul_rn(0.1f,                                     \
                               div_full(__fadd_rn(-vv, it_), tau)), act_);         \
        vv = __fadd_rn(vv, dv_);                                                   \
        SP = (vv >= th) && (rff <= 0.0f);                                          \
        if (SP) vv = rs;                                                           \
        rff = fmaxf(__fsub_rn(SP ? 1.0f : rff, 0.1f), 0.0f);                       \
        add = __fmaf_rn(add, 0.999000499833375f, SP ? 2.0f : 0.0f);                \
    }

// Accumulate W[j, i] for every set bit i (ascending) of mask mm.
// Equivalent to an ascending-k fp32 dot with binary spikes.
#define DOTM(mm, OFF)                                                              \
    {                                                                              \
        unsigned m_ = (mm);                                                        \
        while (m_) {                                                               \
            int i_ = (__ffs(m_) - 1) + (OFF);                                      \
            m_ &= m_ - 1;                                                          \
            a0 = __fadd_rn(a0, Ws[j0 * 81 + i_]);                                  \
            a1 = __fadd_rn(a1, Ws[j1 * 81 + i_]);                                  \
            a2 = __fadd_rn(a2, Ws[j2 * 81 + i_]);                                  \
        }                                                                          \
    }

__global__ void __launch_bounds__(128)
cpg_kernel(const float* __restrict__ v_in,
           const float* __restrict__ refrac_in,
           const float* __restrict__ isyn_in,
           const float* __restrict__ adapt_in,
           const float* __restrict__ noise,
           const float* __restrict__ dmod_p,
           const float* __restrict__ W,
           const float* __restrict__ tau_p,
           const float* __restrict__ vth_p,
           const float* __restrict__ tonic_p,
           const float* __restrict__ reset_p,
           float* __restrict__ v_out,
           float* __restrict__ motor_out)
{
    __shared__ float Ws[N_ * 81];  // row stride 81 (odd) -> conflict-free
    for (int k = threadIdx.x; k < N_ * N_; k += blockDim.x)
        Ws[(k / N_) * 81 + (k % N_)] = W[k];  // full fp32 W
    __syncthreads();

    // exp(-0.1/5), correctly rounded (trace-time constant in the reference)
    const float decay_s = 0.980198673306755f;

    const int lane = threadIdx.x & 31;
    const int b    = blockIdx.x * 4 + (threadIdx.x >> 5);  // one warp = one batch row
    const bool has3 = (lane < 16);
    const int j0 = lane;
    const int j1 = lane + 32;
    const int j2 = has3 ? (lane + 64) : 0;  // dummy row 0 for inactive lanes

    const float dsc = __fmaf_rn(dmod_p[0], 0.5f, 1.0f);

    const float tau0 = tau_p[j0], tau1 = tau_p[j1], tau2 = tau_p[j2];
    const float th0 = vth_p[j0], th1 = vth_p[j1];
    const float th2 = has3 ? vth_p[j2] : 3.0e38f;   // never spikes on dummy lane
    const float dr0 = __fmul_rn(tonic_p[j0], dsc);
    const float dr1 = __fmul_rn(tonic_p[j1], dsc);
    const float dr2 = __fmul_rn(tonic_p[j2], dsc);
    const float rs0 = reset_p[j0], rs1 = reset_p[j1], rs2 = reset_p[j2];

    const int base = b * N_;
    float v0 = v_in[base + j0], v1 = v_in[base + j1], v2 = has3 ? v_in[base + j2] : 0.0f;
    float rf0 = refrac_in[base + j0], rf1 = refrac_in[base + j1],
          rf2 = has3 ? refrac_in[base + j2] : 0.0f;
    float is0 = isyn_in[base + j0], is1 = isyn_in[base + j1],
          is2 = has3 ? isyn_in[base + j2] : 0.0f;
    float ad0 = adapt_in[base + j0], ad1 = adapt_in[base + j1],
          ad2 = has3 ? adapt_in[base + j2] : 0.0f;

    // 4-deep register ring of prefetched noise (hides DRAM latency over ~4 iters)
    float nb[4][3];
#pragma unroll
    for (int k = 0; k < 4; ++k) {
        const float* np = noise + (size_t)k * BN_ + base;
        nb[k][0] = np[j0];
        nb[k][1] = np[j1];
        nb[k][2] = has3 ? np[j2] : 0.0f;
    }

    for (int tc = 0; tc < T_; tc += 4) {
#pragma unroll
        for (int k = 0; k < 4; ++k) {
            const int t = tc + k;
            const float n0 = nb[k][0], n1 = nb[k][1], n2 = nb[k][2];

            const int tp = t + 4;
            if (tp < T_) {  // prefetch noise for t+4 into the freed slot
                const float* np = noise + (size_t)tp * BN_ + base;
                nb[k][0] = np[j0];
                nb[k][1] = np[j1];
                nb[k][2] = has3 ? np[j2] : 0.0f;
            }

            bool sp0, sp1, sp2;
            STEP(v0, rf0, is0, ad0, n0, tau0, th0, dr0, rs0, sp0);
            STEP(v1, rf1, is1, ad1, n1, tau1, th1, dr1, rs1, sp1);
            STEP(v2, rf2, is2, ad2, n2, tau2, th2, dr2, rs2, sp2);

            const unsigned m0 = __ballot_sync(0xffffffffu, sp0);
            const unsigned m1 = __ballot_sync(0xffffffffu, sp1);
            const unsigned m2 = __ballot_sync(0xffffffffu, sp2 && has3);

            // sparse binary matvec: dot_j = sum_{i in spikes} W[j,i], ascending i
            float a0 = 0.0f, a1 = 0.0f, a2 = 0.0f;
            DOTM(m0, 0)
            DOTM(m1, 32)
            DOTM(m2, 64)

            is0 = __fmaf_rn(is0, decay_s, a0);
            is1 = __fmaf_rn(is1, decay_s, a1);
            is2 = __fmaf_rn(is2, decay_s, a2);

            // v trajectory (post-reset v), coalesced across the warp
            float* vo = v_out + (size_t)t * BN_ + base;
            vo[j0] = v0;
            vo[j1] = v1;
            if (has3) vo[lane + 64] = v2;

            // motor output from warp-uniform masks (pure popcount)
            if (lane < 6) {
                float lf = __fmul_rn((float)(__popc(m0 & 0xC0000000u) +
                                             __popc(m1 & 0x00000007u)), 0.2f);
                float le = __fmul_rn((float)__popc(m1 & 0x000000F8u), 0.2f);
                float rfm = __fmul_rn((float)__popc(m2 & 0x000007C0u), 0.2f);
                float rem = __fmul_rn((float)__popc(m2 & 0x0000F800u), 0.2f);
                float mv = lf;
                if (lane == 1) mv = le;
                else if (lane == 2) mv = __fsub_rn(le, lf);
                else if (lane == 3) mv = rfm;
                else if (lane == 4) mv = rem;
                else if (lane == 5) mv = __fsub_rn(rem, rfm);
                motor_out[(size_t)t * (B_ * 6) + b * 6 + lane] = mv;
            }
        }
    }
}

extern "C" void kernel_launch(void* const* d_in, const int* in_sizes, int n_in,
                              void* d_out, int out_size)
{
    const float* v       = (const float*)d_in[0];
    const float* refrac  = (const float*)d_in[1];
    const float* i_syn   = (const float*)d_in[2];
    const float* adapt   = (const float*)d_in[3];
    const float* noise   = (const float*)d_in[4];
    const float* dmod    = (const float*)d_in[5];
    const float* W       = (const float*)d_in[6];
    const float* tau_m   = (const float*)d_in[7];
    const float* v_th    = (const float*)d_in[8];
    const float* tonic   = (const float*)d_in[9];
    const float* reset_v = (const float*)d_in[10];

    float* v_out     = (float*)d_out;                       // [T, B, N]
    float* motor_out = v_out + (size_t)T_ * B_ * N_;        // [T, B, 6]

    // one warp per batch row: 2048 warps = 512 blocks x 4 warps
    cpg_kernel<<<512, 128>>>(v, refrac, i_syn, adapt, noise, dmod, W,
                             tau_m, v_th, tonic, reset_v, v_out, motor_out);
}

// round 8
// speedup vs baseline: 1.1545x; 1.1545x over previous
#include <cuda_runtime.h>

#define B_ 2048
#define N_ 80
#define T_ 400
#define BN_ (B_ * N_)

// LIF step matching the reference's fp32 op order (division via div.full,
// which is what XLA's GPU elemental emitter uses for fp32 divide).
__device__ __forceinline__ float div_full(float a, float b) {
    float r;
    asm("div.full.f32 %0, %1, %2;" : "=f"(r) : "f"(a), "f"(b));
    return r;
}

#define STEP(vv, rff, iss, add, nn, tau, th, dr, rs, SP)                          \
    {                                                                              \
        float it_  = __fadd_rn(__fsub_rn(__fadd_rn(iss, dr), add),                 \
                               __fmul_rn(nn, 0.5f));                               \
        float act_ = (rff <= 0.0f) ? 1.0f : 0.0f;                                  \
        float dv_  = __fmul_rn(__fmul_rn(0.1f,                                     \
                               div_full(__fadd_rn(-vv, it_), tau)), act_);         \
        vv = __fadd_rn(vv, dv_);                                                   \
        SP = (vv >= th) && (rff <= 0.0f);                                          \
        if (SP) vv = rs;                                                           \
        rff = fmaxf(__fsub_rn(SP ? 1.0f : rff, 0.1f), 0.0f);                       \
        add = __fmaf_rn(add, 0.999000499833375f, SP ? 2.0f : 0.0f);                \
    }

// Ascending-i sparse binary dot (bitwise == ascending-k fp32 FADD chain).
#define DOTM(mm, OFF)                                                              \
    {                                                                              \
        unsigned m_ = (mm);                                                        \
        while (m_) {                                                               \
            int i_ = (__ffs(m_) - 1) + (OFF);                                      \
            m_ &= m_ - 1;                                                          \
            a0 = __fadd_rn(a0, Ws[j0 * 81 + i_]);                                  \
            a1 = __fadd_rn(a1, Ws[j1 * 81 + i_]);                                  \
            a2 = __fadd_rn(a2, Ws[j2 * 81 + i_]);                                  \
        }                                                                          \
    }

// One simulated timestep; PREF = compile-time prefetch toggle.
#define BODY(k, PREF)                                                              \
    {                                                                              \
        const float n0 = nb[k][0], n1 = nb[k][1], n2 = nb[k][2];                   \
        if (PREF) { /* refill slot k with t+4's noise via pointer+imm */           \
            nb[k][0] = p0[(k) * BN_];                                              \
            nb[k][1] = p0[(k) * BN_ + 32];                                         \
            nb[k][2] = has3 ? p0[(k) * BN_ + 64] : 0.0f;                           \
        }                                                                          \
        bool sp0, sp1, sp2;                                                        \
        STEP(v0, rf0, is0, ad0, n0, tau0, th0, dr0, rs0, sp0);                     \
        STEP(v1, rf1, is1, ad1, n1, tau1, th1, dr1, rs1, sp1);                     \
        STEP(v2, rf2, is2, ad2, n2, tau2, th2, dr2, rs2, sp2);                     \
        const unsigned m0 = __ballot_sync(0xffffffffu, sp0);                       \
        const unsigned m1 = __ballot_sync(0xffffffffu, sp1);                       \
        const unsigned m2 = __ballot_sync(0xffffffffu, sp2 && has3);               \
        float a0 = 0.0f, a1 = 0.0f, a2 = 0.0f;                                     \
        DOTM(m0, 0)                                                                \
        DOTM(m1, 32)                                                               \
        DOTM(m2, 64)                                                               \
        is0 = __fmaf_rn(is0, decay_s, a0);                                         \
        is1 = __fmaf_rn(is1, decay_s, a1);                                         \
        is2 = __fmaf_rn(is2, decay_s, a2);                                         \
        q0[(k) * BN_] = v0;                                                        \
        q0[(k) * BN_ + 32] = v1;                                                   \
        if (has3) q0[(k) * BN_ + 64] = v2;                                         \
        /* motor: branch-free on all lanes, one predicated store */                \
        float lf = __fmul_rn((float)(__popc(m0 & 0xC0000000u) +                    \
                                     __popc(m1 & 0x00000007u)), 0.2f);             \
        float le = __fmul_rn((float)__popc(m1 & 0x000000F8u), 0.2f);               \
        float rfm = __fmul_rn((float)__popc(m2 & 0x000007C0u), 0.2f);              \
        float rem = __fmul_rn((float)__popc(m2 & 0x0000F800u), 0.2f);              \
        float mv = lf;                                                             \
        if (lane == 1) mv = le;                                                    \
        else if (lane == 2) mv = __fsub_rn(le, lf);                                \
        else if (lane == 3) mv = rfm;                                              \
        else if (lane == 4) mv = rem;                                              \
        else if (lane == 5) mv = __fsub_rn(rem, rfm);                              \
        if (lane < 6) mo[(k) * (B_ * 6)] = mv;                                     \
    }

__global__ void __launch_bounds__(224)
cpg_kernel(const float* __restrict__ v_in,
           const float* __restrict__ refrac_in,
           const float* __restrict__ isyn_in,
           const float* __restrict__ adapt_in,
           const float* __restrict__ noise,
           const float* __restrict__ dmod_p,
           const float* __restrict__ W,
           const float* __restrict__ tau_p,
           const float* __restrict__ vth_p,
           const float* __restrict__ tonic_p,
           const float* __restrict__ reset_p,
           float* __restrict__ v_out,
           float* __restrict__ motor_out)
{
    __shared__ float Ws[N_ * 81];  // row stride 81 (odd) -> conflict-free
    for (int k = threadIdx.x; k < N_ * N_; k += blockDim.x)
        Ws[(k / N_) * 81 + (k % N_)] = W[k];
    __syncthreads();

    // one warp = one batch row; 296 blocks x 7 warps = 2072 slots (24 idle)
    const int b = blockIdx.x * 7 + (threadIdx.x >> 5);
    if (b >= B_) return;

    const float decay_s = 0.980198673306755f;  // exp(-0.1/5), correctly rounded

    const int lane = threadIdx.x & 31;
    const bool has3 = (lane < 16);
    const int j0 = lane;
    const int j1 = lane + 32;
    const int j2 = has3 ? (lane + 64) : 0;  // dummy row 0 for inactive lanes

    const float dsc = __fmaf_rn(dmod_p[0], 0.5f, 1.0f);

    const float tau0 = tau_p[j0], tau1 = tau_p[j1], tau2 = tau_p[j2];
    const float th0 = vth_p[j0], th1 = vth_p[j1];
    const float th2 = has3 ? vth_p[j2] : 3.0e38f;   // never spikes on dummy lane
    const float dr0 = __fmul_rn(tonic_p[j0], dsc);
    const float dr1 = __fmul_rn(tonic_p[j1], dsc);
    const float dr2 = __fmul_rn(tonic_p[j2], dsc);
    const float rs0 = reset_p[j0], rs1 = reset_p[j1], rs2 = reset_p[j2];

    const int base = b * N_;
    float v0 = v_in[base + j0], v1 = v_in[base + j1], v2 = has3 ? v_in[base + j2] : 0.0f;
    float rf0 = refrac_in[base + j0], rf1 = refrac_in[base + j1],
          rf2 = has3 ? refrac_in[base + j2] : 0.0f;
    float is0 = isyn_in[base + j0], is1 = isyn_in[base + j1],
          is2 = has3 ? isyn_in[base + j2] : 0.0f;
    float ad0 = adapt_in[base + j0], ad1 = adapt_in[base + j1],
          ad2 = has3 ? adapt_in[base + j2] : 0.0f;

    // streaming pointers: advanced once per 4-step group; per-step offsets
    // are compile-time immediates (k*BN_*4B <= 2MB fits LDG/STG imm field)
    const float* p0 = noise + base + j0;       // noise[t][b][j0]
    float*       q0 = v_out + base + j0;       // v_out[t][b][j0]
    float*       mo = motor_out + b * 6 + lane; // motor[t][b][lane]

    // 4-deep register ring of prefetched noise
    float nb[4][3];
#pragma unroll
    for (int k = 0; k < 4; ++k) {
        nb[k][0] = p0[k * BN_];
        nb[k][1] = p0[k * BN_ + 32];
        nb[k][2] = has3 ? p0[k * BN_ + 64] : 0.0f;
    }
    p0 += 4 * BN_;  // prefetch window now starts at t=4

    // main loop: 99 groups of 4 steps, unconditional prefetch (max t+4 = 399)
    for (int tc = 0; tc < T_ - 4; tc += 4) {
        BODY(0, 1)
        BODY(1, 1)
        BODY(2, 1)
        BODY(3, 1)
        p0 += 4 * BN_;
        q0 += 4 * BN_;
        mo += 4 * (B_ * 6);
    }
    // epilogue: last 4 steps, no prefetch
    BODY(0, 0)
    BODY(1, 0)
    BODY(2, 0)
    BODY(3, 0)
}

extern "C" void kernel_launch(void* const* d_in, const int* in_sizes, int n_in,
                              void* d_out, int out_size)
{
    const float* v       = (const float*)d_in[0];
    const float* refrac  = (const float*)d_in[1];
    const float* i_syn   = (const float*)d_in[2];
    const float* adapt   = (const float*)d_in[3];
    const float* noise   = (const float*)d_in[4];
    const float* dmod    = (const float*)d_in[5];
    const float* W       = (const float*)d_in[6];
    const float* tau_m   = (const float*)d_in[7];
    const float* v_th    = (const float*)d_in[8];
    const float* tonic   = (const float*)d_in[9];
    const float* reset_v = (const float*)d_in[10];

    float* v_out     = (float*)d_out;                       // [T, B, N]
    float* motor_out = v_out + (size_t)T_ * B_ * N_;        // [T, B, 6]

    // 296 blocks x 7 warps: exactly 2 blocks per SM on 148 SMs -> every SM
    // carries <= ceil(2048/148) = 14 rows (vs 16 on the old 512x4 launch)
    cpg_kernel<<<296, 224>>>(v, refrac, i_syn, adapt, noise, dmod, W,
                             tau_m, v_th, tonic, reset_v, v_out, motor_out);
}

// round 9
// speedup vs baseline: 1.1725x; 1.0156x over previous
#include <cuda_runtime.h>

#define B_ 2048
#define N_ 80
#define T_ 400
#define BN_ (B_ * N_)

// div.full.f32 — the exact instruction XLA's GPU elemental emitter uses for
// fp32 divide. Bit-exactness of the whole simulation hinges on this.
__device__ __forceinline__ float div_full(float a, float b) {
    float r;
    asm("div.full.f32 %0, %1, %2;" : "=f"(r) : "f"(a), "f"(b));
    return r;
}

// LIF step, bitwise-matching the reference. The active-gate is applied as a
// predicated add: reference computes v + (x*act) with act in {0,1}; act=0
// gives v + (+/-0) == v, so skipping the add is exact.
#define STEP(vv, rff, iss, add, nn, tau, th, dr, rs, SP)                          \
    {                                                                              \
        float it_  = __fadd_rn(__fsub_rn(__fadd_rn(iss, dr), add),                 \
                               __fmul_rn(nn, 0.5f));                               \
        bool  act_ = (rff <= 0.0f);                                                \
        float dv_  = __fmul_rn(0.1f, div_full(__fadd_rn(-vv, it_), tau));          \
        if (act_) vv = __fadd_rn(vv, dv_);                                         \
        SP = (vv >= th) && act_;                                                   \
        if (SP) vv = rs;                                                           \
        rff = fmaxf(__fsub_rn(SP ? 1.0f : rff, 0.1f), 0.0f);                       \
        add = __fmaf_rn(add, 0.999000499833375f, SP ? 2.0f : 0.0f);                \
    }

// Ascending-i sparse binary dot; one LDS.128 per spike fetches the W values
// for all three of this lane's rows. Same values, same FADD order as before
// -> bitwise identical to the ascending-k fp32 chain.
#define DOTM(mm, OFF)                                                              \
    {                                                                              \
        unsigned m_ = (mm);                                                        \
        while (m_) {                                                               \
            int i_ = (__ffs(m_) - 1) + (OFF);                                      \
            m_ &= m_ - 1;                                                          \
            float4 w_ = Ws2[i_ * 32 + lane];                                       \
            a0 = __fadd_rn(a0, w_.x);                                              \
            a1 = __fadd_rn(a1, w_.y);                                              \
            a2 = __fadd_rn(a2, w_.z);                                              \
        }                                                                          \
    }

// One simulated timestep; PREF = compile-time prefetch toggle.
#define BODY(k, PREF)                                                              \
    {                                                                              \
        const float n0 = nb[k][0], n1 = nb[k][1], n2 = nb[k][2];                   \
        if (PREF) {                                                                \
            nb[k][0] = p0[(k) * BN_];                                              \
            nb[k][1] = p0[(k) * BN_ + 32];                                         \
            nb[k][2] = has3 ? p0[(k) * BN_ + 64] : 0.0f;                           \
        }                                                                          \
        bool sp0, sp1, sp2;                                                        \
        STEP(v0, rf0, is0, ad0, n0, tau0, th0, dr0, rs0, sp0);                     \
        STEP(v1, rf1, is1, ad1, n1, tau1, th1, dr1, rs1, sp1);                     \
        STEP(v2, rf2, is2, ad2, n2, tau2, th2, dr2, rs2, sp2);                     \
        const unsigned m0 = __ballot_sync(0xffffffffu, sp0);                       \
        const unsigned m1 = __ballot_sync(0xffffffffu, sp1);                       \
        const unsigned m2 = __ballot_sync(0xffffffffu, sp2 && has3);               \
        float a0 = 0.0f, a1 = 0.0f, a2 = 0.0f;                                     \
        DOTM(m0, 0)                                                                \
        DOTM(m1, 32)                                                               \
        DOTM(m2, 64)                                                               \
        is0 = __fmaf_rn(is0, decay_s, a0);                                         \
        is1 = __fmaf_rn(is1, decay_s, a1);                                         \
        is2 = __fmaf_rn(is2, decay_s, a2);                                         \
        q0[(k) * BN_] = v0;                                                        \
        q0[(k) * BN_ + 32] = v1;                                                   \
        if (has3) q0[(k) * BN_ + 64] = v2;                                         \
        float lf = __fmul_rn((float)(__popc(m0 & 0xC0000000u) +                    \
                                     __popc(m1 & 0x00000007u)), 0.2f);             \
        float le = __fmul_rn((float)__popc(m1 & 0x000000F8u), 0.2f);               \
        float rfm = __fmul_rn((float)__popc(m2 & 0x000007C0u), 0.2f);              \
        float rem = __fmul_rn((float)__popc(m2 & 0x0000F800u), 0.2f);              \
        float mv = lf;                                                             \
        if (lane == 1) mv = le;                                                    \
        else if (lane == 2) mv = __fsub_rn(le, lf);                                \
        else if (lane == 3) mv = rfm;                                              \
        else if (lane == 4) mv = rem;                                              \
        else if (lane == 5) mv = __fsub_rn(rem, rfm);                              \
        if (lane < 6) mo[(k) * (B_ * 6)] = mv;                                     \
    }

__global__ void __launch_bounds__(224)
cpg_kernel(const float* __restrict__ v_in,
           const float* __restrict__ refrac_in,
           const float* __restrict__ isyn_in,
           const float* __restrict__ adapt_in,
           const float* __restrict__ noise,
           const float* __restrict__ dmod_p,
           const float* __restrict__ W,
           const float* __restrict__ tau_p,
           const float* __restrict__ vth_p,
           const float* __restrict__ tonic_p,
           const float* __restrict__ reset_p,
           float* __restrict__ v_out,
           float* __restrict__ motor_out)
{
    // Ws2[i][lane] = (W[lane,i], W[lane+32,i], lane<16 ? W[lane+64,i] : 0, pad)
    // One LDS.128 per spike serves all 3 rows; lanes contiguous -> conflict-free.
    __shared__ float4 Ws2[N_ * 32];
    for (int idx = threadIdx.x; idx < N_ * 32; idx += blockDim.x) {
        int i = idx >> 5, l = idx & 31;
        float x = W[l * N_ + i];
        float y = W[(l + 32) * N_ + i];
        float z = (l < 16) ? W[(l + 64) * N_ + i] : 0.0f;
        Ws2[idx] = make_float4(x, y, z, 0.0f);
    }
    __syncthreads();

    // one warp = one batch row; 296 blocks x 7 warps = 2072 slots (24 idle)
    const int b = blockIdx.x * 7 + (threadIdx.x >> 5);
    if (b >= B_) return;

    const float decay_s = 0.980198673306755f;  // exp(-0.1/5), correctly rounded

    const int lane = threadIdx.x & 31;
    const bool has3 = (lane < 16);
    const int j0 = lane;
    const int j1 = lane + 32;
    const int j2 = has3 ? (lane + 64) : 0;  // dummy for state loads on hi lanes

    const float dsc = __fmaf_rn(dmod_p[0], 0.5f, 1.0f);

    const float tau0 = tau_p[j0], tau1 = tau_p[j1], tau2 = tau_p[j2];
    const float th0 = vth_p[j0], th1 = vth_p[j1];
    const float th2 = has3 ? vth_p[j2] : 3.0e38f;   // never spikes on dummy lane
    const float dr0 = __fmul_rn(tonic_p[j0], dsc);
    const float dr1 = __fmul_rn(tonic_p[j1], dsc);
    const float dr2 = __fmul_rn(tonic_p[j2], dsc);
    const float rs0 = reset_p[j0], rs1 = reset_p[j1], rs2 = reset_p[j2];

    const int base = b * N_;
    float v0 = v_in[base + j0], v1 = v_in[base + j1], v2 = has3 ? v_in[base + j2] : 0.0f;
    float rf0 = refrac_in[base + j0], rf1 = refrac_in[base + j1],
          rf2 = has3 ? refrac_in[base + j2] : 0.0f;
    float is0 = isyn_in[base + j0], is1 = isyn_in[base + j1],
          is2 = has3 ? isyn_in[base + j2] : 0.0f;
    float ad0 = adapt_in[base + j0], ad1 = adapt_in[base + j1],
          ad2 = has3 ? adapt_in[base + j2] : 0.0f;

    // streaming pointers, advanced once per 4-step group (offsets = immediates)
    const float* p0 = noise + base + j0;
    float*       q0 = v_out + base + j0;
    float*       mo = motor_out + b * 6 + lane;

    // 4-deep register ring of prefetched noise
    float nb[4][3];
#pragma unroll
    for (int k = 0; k < 4; ++k) {
        nb[k][0] = p0[k * BN_];
        nb[k][1] = p0[k * BN_ + 32];
        nb[k][2] = has3 ? p0[k * BN_ + 64] : 0.0f;
    }
    p0 += 4 * BN_;

    for (int tc = 0; tc < T_ - 4; tc += 4) {
        BODY(0, 1)
        BODY(1, 1)
        BODY(2, 1)
        BODY(3, 1)
        p0 += 4 * BN_;
        q0 += 4 * BN_;
        mo += 4 * (B_ * 6);
    }
    BODY(0, 0)
    BODY(1, 0)
    BODY(2, 0)
    BODY(3, 0)
}

extern "C" void kernel_launch(void* const* d_in, const int* in_sizes, int n_in,
                              void* d_out, int out_size)
{
    const float* v       = (const float*)d_in[0];
    const float* refrac  = (const float*)d_in[1];
    const float* i_syn   = (const float*)d_in[2];
    const float* adapt   = (const float*)d_in[3];
    const float* noise   = (const float*)d_in[4];
    const float* dmod    = (const float*)d_in[5];
    const float* W       = (const float*)d_in[6];
    const float* tau_m   = (const float*)d_in[7];
    const float* v_th    = (const float*)d_in[8];
    const float* tonic   = (const float*)d_in[9];
    const float* reset_v = (const float*)d_in[10];

    float* v_out     = (float*)d_out;                       // [T, B, N]
    float* motor_out = v_out + (size_t)T_ * B_ * N_;        // [T, B, 6]

    // 296 blocks x 7 warps: 2 blocks/SM on 148 SMs, every SM <= 14 rows
    cpg_kernel<<<296, 224>>>(v, refrac, i_syn, adapt, noise, dmod, W,
                             tau_m, v_th, tonic, reset_v, v_out, motor_out);
}